// round 15
// baseline (speedup 1.0000x reference)
#include <cuda_runtime.h>
#include <cuda_bf16.h>
#include <cstdint>

// ============================================================================
// BinaryLinearWscales (GB300). Warp-specialized dual-pipe GEMM, rebalanced:
//   warps 0-7  (mma): level-1 q1 x sign, cols 0..47  -> tensor pipe (3072 cyc)
//   warps 8-15 (dp):  level-2 q2 x sign, cols 0..63  -> fma pipe
//                   + level-1 q1 x sign, cols 48..63 (2 cols per dp warp)
//   x ~= alpha_m * (q1 + q2/254), sign(W) exact in s8.
// R14 proved specialization overlaps the pipes (tensor 78% + fma 39%);
// this round equalizes pipe busy times (c=48 split).
// ============================================================================

// ---------------- device scratch (pre-swizzled tiled s8) --------------------
__device__ __align__(16384) int8_t g_a0[16777216];   // 16 MB: q1 of x
__device__ __align__(16384) int8_t g_a1[16777216];   // 16 MB: q2 of x
__device__ __align__(16384) int8_t g_b [16777216];   // 16 MB: sign(W)
__device__ float g_scale [4096];
__device__ float g_rowsum[4096];

// ---------------- PTX helpers ------------------------------------------------
static __device__ __forceinline__ uint32_t smem_u32(const void* p) {
    uint32_t a;
    asm("{ .reg .u64 t; cvta.to.shared.u64 t, %1; cvt.u32.u64 %0, t; }" : "=r"(a) : "l"(p));
    return a;
}

#define MBARRIER_INIT(addr, cnt) \
    asm volatile("mbarrier.init.shared.b64 [%0], %1;" :: "r"((uint32_t)(addr)), "r"((uint32_t)(cnt)) : "memory")

#define MBARRIER_EXPECT_TX(addr, bytes) \
    asm volatile("mbarrier.arrive.expect_tx.shared.b64 _, [%0], %1;" :: "r"((uint32_t)(addr)), "r"((uint32_t)(bytes)) : "memory")

#define MBARRIER_ARRIVE(addr) \
    asm volatile("mbarrier.arrive.shared.b64 _, [%0];" :: "r"((uint32_t)(addr)) : "memory")

#define MBARRIER_WAIT_PARITY(mbar_addr, parity) do {                               \
    uint32_t _m = (uint32_t)(mbar_addr); uint32_t _p = (uint32_t)(parity);         \
    uint32_t _d;                                                                    \
    asm volatile("{\n\t.reg .pred p;\n\t"                                           \
        "mbarrier.try_wait.parity.acquire.cta.shared::cta.b64 p, [%1], %2;\n\t"     \
        "selp.b32 %0, 1, 0, p;\n\t}" : "=r"(_d) : "r"(_m), "r"(_p) : "memory");     \
    if (!_d) {                                                                      \
        asm volatile("{\n\t.reg .pred P1;\n\t"                                      \
        "WL_%=:\n\t"                                                                \
        "mbarrier.try_wait.parity.acquire.cta.shared::cta.b64 P1, [%0], %1, 0x989680;\n\t" \
        "@P1 bra.uni WD_%=;\n\t"                                                    \
        "bra.uni WL_%=;\n\t"                                                        \
        "WD_%=:\n\t}" :: "r"(_m), "r"(_p) : "memory");                              \
    }                                                                               \
} while (0)

#define MBARRIER_WAIT_PARITY_RELAXED(mbar_addr, parity) do {                       \
    uint32_t _m = (uint32_t)(mbar_addr); uint32_t _p = (uint32_t)(parity);         \
    uint32_t _d;                                                                    \
    asm volatile("{\n\t.reg .pred p;\n\t"                                           \
        "mbarrier.try_wait.parity.relaxed.cta.shared::cta.b64 p, [%1], %2, 0x989680;\n\t" \
        "selp.b32 %0, 1, 0, p;\n\t}" : "=r"(_d) : "r"(_m), "r"(_p) : "memory");     \
    if (!_d) {                                                                      \
        asm volatile("{\n\t.reg .pred P1;\n\t"                                      \
        "WL_%=:\n\t"                                                                \
        "mbarrier.try_wait.parity.relaxed.cta.shared::cta.b64 P1, [%0], %1, 0x989680;\n\t" \
        "@P1 bra.uni WD_%=;\n\t"                                                    \
        "bra.uni WL_%=;\n\t"                                                        \
        "WD_%=:\n\t}" :: "r"(_m), "r"(_p) : "memory");                              \
    }                                                                               \
} while (0)

static __device__ __forceinline__ void bulk_g2s(uint32_t dst, const void* src,
                                                uint32_t bytes, uint32_t mbar) {
    asm volatile(
        "cp.async.bulk.shared::cluster.global.mbarrier::complete_tx::bytes [%0], [%1], %2, [%3];"
        :: "r"(dst), "l"(src), "r"(bytes), "r"(mbar) : "memory");
}

static __device__ __forceinline__ void ldsm4(uint32_t* r, uint32_t addr) {
    asm volatile("ldmatrix.sync.aligned.m8n8.x4.shared.b16 {%0,%1,%2,%3}, [%4];"
        : "=r"(r[0]), "=r"(r[1]), "=r"(r[2]), "=r"(r[3]) : "r"(addr));
}

static __device__ __forceinline__ void imma(int* d, const uint32_t* a,
                                            uint32_t b0, uint32_t b1) {
    asm volatile(
        "mma.sync.aligned.m16n8k32.row.col.s32.s8.s8.s32 "
        "{%0,%1,%2,%3}, {%4,%5,%6,%7}, {%8,%9}, {%0,%1,%2,%3};"
        : "+r"(d[0]), "+r"(d[1]), "+r"(d[2]), "+r"(d[3])
        : "r"(a[0]), "r"(a[1]), "r"(a[2]), "r"(a[3]), "r"(b0), "r"(b1));
}

static __device__ __forceinline__ void dp4x4(int* acc, const int4& a, const int4& b) {
    *acc = __dp4a(a.x, b.x, *acc);
    *acc = __dp4a(a.y, b.y, *acc);
    *acc = __dp4a(a.z, b.z, *acc);
    *acc = __dp4a(a.w, b.w, *acc);
}

// ---------------- geometry ----------------------------------------------------
static constexpr int      NCHUNK      = 32;       // 4096 / 128
static constexpr uint32_t TILE_BYTES  = 16384;    // 128 rows x 128 k-bytes
static constexpr uint32_t BTILE_BYTES = 8192;     // 64 rows x 128 k-bytes
static constexpr int      STAGES      = 4;
static constexpr uint32_t OFF_A1      = 16384;
static constexpr uint32_t OFF_B       = 32768;
static constexpr uint32_t STAGE_BYTES = 40960;    // A0 16K + A1 16K + B 8K
static constexpr uint32_t OFF_FULL    = 0;
static constexpr uint32_t OFF_EMPTY   = 64;
static constexpr uint32_t OFF_STAGE   = 1024;
static constexpr uint32_t SMEM_DYN    = OFF_STAGE + STAGES * STAGE_BYTES;  // 164864

// ---------------- merged prologue: pack x (y=0) and sign(W) (y=1) ------------
__global__ void __launch_bounds__(256) prep_kernel(const float* __restrict__ x,
                                                   const float* __restrict__ w) {
    const int row = blockIdx.x;
    const int tid = threadIdx.x;
    const bool is_x = (blockIdx.y == 0);
    const float* src = (is_x ? x : w) + (size_t)row * 4096;

    float4 v[4];
    #pragma unroll
    for (int i = 0; i < 4; i++) v[i] = ((const float4*)src)[tid * 4 + i];

    const uint32_t inrow = (uint32_t)((tid & 7) * 16);
    const uint32_t swzc  = inrow ^ (uint32_t)((row & 7) << 4);
    const size_t off = ((size_t)(row >> 7) * 32 + (size_t)(tid >> 3)) * TILE_BYTES
                     + (size_t)((row & 127) * 128) + swzc;

    if (is_x) {
        float mx = 0.f, sm = 0.f;
        #pragma unroll
        for (int i = 0; i < 4; i++) {
            mx = fmaxf(mx, fmaxf(fmaxf(fabsf(v[i].x), fabsf(v[i].y)),
                                 fmaxf(fabsf(v[i].z), fabsf(v[i].w))));
            sm += (v[i].x + v[i].y) + (v[i].z + v[i].w);
        }
        __shared__ float smax[256], ssum[256];
        smax[tid] = mx; ssum[tid] = sm;
        __syncthreads();
        for (int s = 128; s > 0; s >>= 1) {
            if (tid < s) {
                smax[tid] = fmaxf(smax[tid], smax[tid + s]);
                ssum[tid] += ssum[tid + s];
            }
            __syncthreads();
        }
        const float maxv = smax[0];
        const float inv  = (maxv > 0.f) ? 127.f / maxv : 0.f;

        uint32_t p1[4], p2[4];
        #pragma unroll
        for (int i = 0; i < 4; i++) {
            float e[4] = {v[i].x, v[i].y, v[i].z, v[i].w};
            uint32_t w1 = 0, w2 = 0;
            #pragma unroll
            for (int b = 0; b < 4; b++) {
                float r0 = e[b] * inv;
                int q1 = __float2int_rn(r0);
                int q2 = __float2int_rn((r0 - (float)q1) * 254.f);
                w1 |= (uint32_t)(q1 & 0xff) << (8 * b);
                w2 |= (uint32_t)(q2 & 0xff) << (8 * b);
            }
            p1[i] = w1; p2[i] = w2;
        }
        *(uint4*)((char*)g_a0 + off) = make_uint4(p1[0], p1[1], p1[2], p1[3]);
        *(uint4*)((char*)g_a1 + off) = make_uint4(p2[0], p2[1], p2[2], p2[3]);
        if (tid == 0) {
            g_scale[row]  = (maxv > 0.f) ? maxv / 127.f : 0.f;
            g_rowsum[row] = ssum[0];
        }
    } else {
        uint32_t p[4];
        #pragma unroll
        for (int i = 0; i < 4; i++) {
            float e[4] = {v[i].x, v[i].y, v[i].z, v[i].w};
            uint32_t wq = 0;
            #pragma unroll
            for (int b = 0; b < 4; b++) {
                int q = (e[b] > 0.f) ? 1 : ((e[b] < 0.f) ? -1 : 0);
                wq |= (uint32_t)(q & 0xff) << (8 * b);
            }
            p[i] = wq;
        }
        *(uint4*)((char*)g_b + off) = make_uint4(p[0], p[1], p[2], p[3]);
    }
}

// ---------------- main GEMM ----------------------------------------------------
// grid (64 ntile, 32 mtile), 512 threads. CTA tile 128M x 64N.
// warps 0-7 (mma): warp w -> rows 16w..16w+15, cols 0..47 (warp tile 16x48).
// warps 8-15 (dp): warp d -> level-2 cols 8d..8d+7 + level-1 cols 48+2d,49+2d;
//                  lane -> rows {lane+32i}.
__global__ void __launch_bounds__(512, 1)
gemm_kernel(const float* __restrict__ wscale, const float* __restrict__ wbias,
            float* __restrict__ out) {
    extern __shared__ __align__(1024) char smem[];
    const uint32_t sb = smem_u32(smem);
    const int tid = threadIdx.x;
    const int wid = tid >> 5;
    const int lane = tid & 31;
    const int ntile = blockIdx.x;   // 0..63
    const int mtile = blockIdx.y;   // 0..31

    const char* pa0 = (const char*)g_a0 + (size_t)mtile * (32u * TILE_BYTES);
    const char* pa1 = (const char*)g_a1 + (size_t)mtile * (32u * TILE_BYTES);
    const char* pb  = (const char*)g_b  + (size_t)(ntile >> 1) * (32u * TILE_BYTES)
                    + (size_t)(ntile & 1) * BTILE_BYTES;

    if (tid == 0) {
        #pragma unroll
        for (int s = 0; s < STAGES; s++) {
            MBARRIER_INIT(sb + OFF_FULL  + 8u * s, 1);
            MBARRIER_INIT(sb + OFF_EMPTY + 8u * s, 16);
        }
    }
    __syncthreads();

    if (tid == 0) {
        #pragma unroll
        for (int s = 0; s < STAGES; s++) {
            uint32_t fb = sb + OFF_FULL + 8u * s;
            MBARRIER_EXPECT_TX(fb, STAGE_BYTES);
            uint32_t dst = sb + OFF_STAGE + (uint32_t)s * STAGE_BYTES;
            size_t co = (size_t)s * TILE_BYTES;
            bulk_g2s(dst,          pa0 + co, TILE_BYTES,  fb);
            bulk_g2s(dst + OFF_A1, pa1 + co, TILE_BYTES,  fb);
            bulk_g2s(dst + OFF_B,  pb  + co, BTILE_BYTES, fb);
        }
    }

    if (wid < 8) {
        // ============ MMA warps: level-1, cols 0..47, warp tile 16x48 ===========
        const int rA = lane & 15;
        const uint32_t hb = (uint32_t)((lane >> 4) * 16);
        const uint32_t ph_sw = (uint32_t)((rA & 7) << 4);

        const uint32_t rowA = (uint32_t)((wid * 16 + rA) * 128);
        uint32_t rowB[3];
        #pragma unroll
        for (int j = 0; j < 3; j++) rowB[j] = (uint32_t)((j * 16 + rA) * 128);
        uint32_t colx[4];
        #pragma unroll
        for (int ks = 0; ks < 4; ks++) colx[ks] = ((uint32_t)(ks * 32) + hb) ^ ph_sw;

        int acc0[6][4];                   // 24 regs: 6 n8-tiles of cols 0..47
        #pragma unroll
        for (int u = 0; u < 6; u++)
            #pragma unroll
            for (int i = 0; i < 4; i++) acc0[u][i] = 0;

        for (int ch = 0; ch < NCHUNK; ch++) {
            const int st = ch & 3;
            const int ph = (ch >> 2) & 1;
            MBARRIER_WAIT_PARITY(sb + OFF_FULL + 8u * st, ph);
            const uint32_t SA0 = sb + OFF_STAGE + (uint32_t)st * STAGE_BYTES;
            const uint32_t SB  = SA0 + OFF_B;

            #pragma unroll
            for (int ks = 0; ks < 4; ks++) {
                uint32_t a0f[4], bf[3][4];
                ldsm4(a0f, SA0 + rowA + colx[ks]);
                #pragma unroll
                for (int j = 0; j < 3; j++) ldsm4(bf[j], SB + rowB[j] + colx[ks]);
                #pragma unroll
                for (int j = 0; j < 3; j++) {
                    imma(acc0[2 * j],     a0f, bf[j][0], bf[j][2]);
                    imma(acc0[2 * j + 1], a0f, bf[j][1], bf[j][3]);
                }
            }
            if (lane == 0) MBARRIER_ARRIVE(sb + OFF_EMPTY + 8u * st);
            if (tid == 0 && ch + STAGES < NCHUNK) {
                MBARRIER_WAIT_PARITY_RELAXED(sb + OFF_EMPTY + 8u * st, ph);
                uint32_t fb = sb + OFF_FULL + 8u * st;
                MBARRIER_EXPECT_TX(fb, STAGE_BYTES);
                uint32_t dst = sb + OFF_STAGE + (uint32_t)st * STAGE_BYTES;
                size_t co = (size_t)(ch + STAGES) * TILE_BYTES;
                bulk_g2s(dst,          pa0 + co, TILE_BYTES,  fb);
                bulk_g2s(dst + OFF_A1, pa1 + co, TILE_BYTES,  fb);
                bulk_g2s(dst + OFF_B,  pb  + co, BTILE_BYTES, fb);
            }
        }

        // ---- epilogue: combine + store rows 16*wid..16*wid+15, all 64 cols ----
        __syncthreads();                   // all warps done with stage buffers
        __syncthreads();                   // sL/sP written by dp warps
        const int* sL = (const int*)smem;            // 128 x 68: level-2
        const int* sP = (const int*)(smem + 34816);  // 128 x 20: level-1 cols-48
        const float inv254 = 1.f / 254.f;
        const int lg = lane >> 2;
        const int lc = (lane & 3) * 2;
        #pragma unroll
        for (int half = 0; half < 2; half++) {
            const int ml = wid * 16 + lg + half * 8;
            const int m  = mtile * 128 + ml;
            const float alpha = g_scale[m];
            const float rs    = g_rowsum[m];
            float* orow = out + (size_t)m * 4096;
            const int i0 = half * 2, i1 = half * 2 + 1;
            #pragma unroll
            for (int u = 0; u < 6; u++) {
                const int nl = u * 8 + lc;
                const int n  = ntile * 64 + nl;
                float v0 = (float)acc0[u][i0] + (float)sL[ml * 68 + nl]     * inv254;
                float v1 = (float)acc0[u][i1] + (float)sL[ml * 68 + nl + 1] * inv254;
                float2 o;
                o.x = __ldg(wscale + n)     * (alpha * v0) + __ldg(wbias + n)     * rs;
                o.y = __ldg(wscale + n + 1) * (alpha * v1) + __ldg(wbias + n + 1) * rs;
                *(float2*)(orow + n) = o;
            }
            #pragma unroll
            for (int u = 0; u < 2; u++) {
                const int nl = 48 + u * 8 + lc;
                const int n  = ntile * 64 + nl;
                float v0 = (float)sP[ml * 20 + (nl - 48)]
                         + (float)sL[ml * 68 + nl]     * inv254;
                float v1 = (float)sP[ml * 20 + (nl - 47)]
                         + (float)sL[ml * 68 + nl + 1] * inv254;
                float2 o;
                o.x = __ldg(wscale + n)     * (alpha * v0) + __ldg(wbias + n)     * rs;
                o.y = __ldg(wscale + n + 1) * (alpha * v1) + __ldg(wbias + n + 1) * rs;
                *(float2*)(orow + n) = o;
            }
        }
    } else {
        // ===== DP warps: level-2 (8 cols) + level-1 (2 cols of 48..63) =========
        const int dwid = wid - 8;                     // 0..7
        const int c1a = 48 + 2 * dwid;                // level-1 col pair
        const uint32_t aswz = (uint32_t)((lane & 7) * 16);
        const uint32_t sw1a = (uint32_t)((c1a & 7) * 16);
        const uint32_t sw1b = (uint32_t)(((c1a + 1) & 7) * 16);

        int accL[4][8];                    // level-2 (32 regs)
        int accP[4][2];                    // level-1 extra cols (8 regs)
        #pragma unroll
        for (int i = 0; i < 4; i++) {
            #pragma unroll
            for (int j = 0; j < 8; j++) accL[i][j] = 0;
            accP[i][0] = 0; accP[i][1] = 0;
        }

        for (int ch = 0; ch < NCHUNK; ch++) {
            const int st = ch & 3;
            const int ph = (ch >> 2) & 1;
            MBARRIER_WAIT_PARITY(sb + OFF_FULL + 8u * st, ph);
            const char* cSA0 = smem + OFF_STAGE + (uint32_t)st * STAGE_BYTES;
            const char* cSA1 = cSA0 + OFF_A1;
            const char* cSB  = cSA0 + OFF_B;

            #pragma unroll
            for (int ks = 0; ks < 4; ks++) {
                #pragma unroll
                for (int sub = 0; sub < 2; sub++) {
                    const uint32_t col = (uint32_t)(ks * 32 + sub * 16);
                    const uint32_t ca = col ^ aswz;
                    int4 a1[4], a0[4];
                    #pragma unroll
                    for (int i = 0; i < 4; i++) {
                        a1[i] = *(const int4*)(cSA1 + (lane + 32 * i) * 128 + ca);
                        a0[i] = *(const int4*)(cSA0 + (lane + 32 * i) * 128 + ca);
                    }
                    #pragma unroll
                    for (int j = 0; j < 8; j++) {
                        const int4 b4 = *(const int4*)(cSB + (dwid * 8 + j) * 128
                                                       + (col ^ (uint32_t)(j * 16)));
                        #pragma unroll
                        for (int i = 0; i < 4; i++) dp4x4(&accL[i][j], a1[i], b4);
                    }
                    const int4 bp0 = *(const int4*)(cSB + c1a * 128 + (col ^ sw1a));
                    const int4 bp1 = *(const int4*)(cSB + (c1a + 1) * 128 + (col ^ sw1b));
                    #pragma unroll
                    for (int i = 0; i < 4; i++) {
                        dp4x4(&accP[i][0], a0[i], bp0);
                        dp4x4(&accP[i][1], a0[i], bp1);
                    }
                }
            }
            if (lane == 0) MBARRIER_ARRIVE(sb + OFF_EMPTY + 8u * st);
        }

        // ---- publish dp sums for the mma warps ----
        __syncthreads();                   // everyone done with stage buffers
        int* sL = (int*)smem;              // 128 x 68
        int* sP = (int*)(smem + 34816);    // 128 x 20
        #pragma unroll
        for (int i = 0; i < 4; i++) {
            const int row = lane + 32 * i;
            #pragma unroll
            for (int j = 0; j < 8; j++)
                sL[row * 68 + (dwid * 8 + j)] = accL[i][j];
            sP[row * 20 + (c1a - 48)]     = accP[i][0];
            sP[row * 20 + (c1a - 48) + 1] = accP[i][1];
        }
        __syncthreads();
    }
}

// ---------------- launch --------------------------------------------------------
extern "C" void kernel_launch(void* const* d_in, const int* in_sizes, int n_in,
                              void* d_out, int out_size) {
    (void)in_sizes; (void)n_in; (void)out_size;
    const float* x      = (const float*)d_in[0];   // [2,2048,4096]
    const float* weight = (const float*)d_in[1];   // [4096,4096]
    const float* wscale = (const float*)d_in[2];   // [4096,1]
    const float* wbias  = (const float*)d_in[3];   // [4096,1]
    float* out = (float*)d_out;

    cudaFuncSetAttribute(gemm_kernel, cudaFuncAttributeMaxDynamicSharedMemorySize,
                         (int)SMEM_DYN);

    prep_kernel<<<dim3(4096, 2), 256>>>(x, weight);
    gemm_kernel<<<dim3(64, 32), 512, SMEM_DYN>>>(wscale, wbias, out);
}

// round 16
// speedup vs baseline: 1.1593x; 1.1593x over previous
#include <cuda_runtime.h>
#include <cuda_bf16.h>
#include <cstdint>

// ============================================================================
// BinaryLinearWscales (GB300). Warp-specialized dual-pipe GEMM, 2 CTAs/SM:
//   warps 0-3 (mma): level-1 q1 x sign, all 64 cols -> tensor pipe
//   warps 4-7 (dp):  level-2 q2 x sign, all 64 cols -> fma pipe
//   x ~= alpha_m * (q1 + q2/254), sign(W) exact in s8.
// R14 (1 CTA/SM, 512 thr) hit tensor 78% with 22% idle from issue bubbles;
// this round: 256-thr CTAs, 64Mx64N tile, 97KB smem -> 2 CTAs/SM so two
// decoupled pipelines keep the SM-shared tensor unit fed.
// ============================================================================

// ---------------- device scratch (pre-swizzled tiled s8) --------------------
// Layout: [tile(128 rows)][kchunk(128 bytes)] -> 16KB per chunk-block.
__device__ __align__(16384) int8_t g_a0[16777216];   // 16 MB: q1 of x
__device__ __align__(16384) int8_t g_a1[16777216];   // 16 MB: q2 of x
__device__ __align__(16384) int8_t g_b [16777216];   // 16 MB: sign(W)
__device__ float g_scale [4096];
__device__ float g_rowsum[4096];

// ---------------- PTX helpers ------------------------------------------------
static __device__ __forceinline__ uint32_t smem_u32(const void* p) {
    uint32_t a;
    asm("{ .reg .u64 t; cvta.to.shared.u64 t, %1; cvt.u32.u64 %0, t; }" : "=r"(a) : "l"(p));
    return a;
}

#define MBARRIER_INIT(addr, cnt) \
    asm volatile("mbarrier.init.shared.b64 [%0], %1;" :: "r"((uint32_t)(addr)), "r"((uint32_t)(cnt)) : "memory")

#define MBARRIER_EXPECT_TX(addr, bytes) \
    asm volatile("mbarrier.arrive.expect_tx.shared.b64 _, [%0], %1;" :: "r"((uint32_t)(addr)), "r"((uint32_t)(bytes)) : "memory")

#define MBARRIER_ARRIVE(addr) \
    asm volatile("mbarrier.arrive.shared.b64 _, [%0];" :: "r"((uint32_t)(addr)) : "memory")

#define MBARRIER_WAIT_PARITY(mbar_addr, parity) do {                               \
    uint32_t _m = (uint32_t)(mbar_addr); uint32_t _p = (uint32_t)(parity);         \
    uint32_t _d;                                                                    \
    asm volatile("{\n\t.reg .pred p;\n\t"                                           \
        "mbarrier.try_wait.parity.acquire.cta.shared::cta.b64 p, [%1], %2;\n\t"     \
        "selp.b32 %0, 1, 0, p;\n\t}" : "=r"(_d) : "r"(_m), "r"(_p) : "memory");     \
    if (!_d) {                                                                      \
        asm volatile("{\n\t.reg .pred P1;\n\t"                                      \
        "WL_%=:\n\t"                                                                \
        "mbarrier.try_wait.parity.acquire.cta.shared::cta.b64 P1, [%0], %1, 0x989680;\n\t" \
        "@P1 bra.uni WD_%=;\n\t"                                                    \
        "bra.uni WL_%=;\n\t"                                                        \
        "WD_%=:\n\t}" :: "r"(_m), "r"(_p) : "memory");                              \
    }                                                                               \
} while (0)

#define MBARRIER_WAIT_PARITY_RELAXED(mbar_addr, parity) do {                       \
    uint32_t _m = (uint32_t)(mbar_addr); uint32_t _p = (uint32_t)(parity);         \
    uint32_t _d;                                                                    \
    asm volatile("{\n\t.reg .pred p;\n\t"                                           \
        "mbarrier.try_wait.parity.relaxed.cta.shared::cta.b64 p, [%1], %2, 0x989680;\n\t" \
        "selp.b32 %0, 1, 0, p;\n\t}" : "=r"(_d) : "r"(_m), "r"(_p) : "memory");     \
    if (!_d) {                                                                      \
        asm volatile("{\n\t.reg .pred P1;\n\t"                                      \
        "WL_%=:\n\t"                                                                \
        "mbarrier.try_wait.parity.relaxed.cta.shared::cta.b64 P1, [%0], %1, 0x989680;\n\t" \
        "@P1 bra.uni WD_%=;\n\t"                                                    \
        "bra.uni WL_%=;\n\t"                                                        \
        "WD_%=:\n\t}" :: "r"(_m), "r"(_p) : "memory");                              \
    }                                                                               \
} while (0)

static __device__ __forceinline__ void bulk_g2s(uint32_t dst, const void* src,
                                                uint32_t bytes, uint32_t mbar) {
    asm volatile(
        "cp.async.bulk.shared::cluster.global.mbarrier::complete_tx::bytes [%0], [%1], %2, [%3];"
        :: "r"(dst), "l"(src), "r"(bytes), "r"(mbar) : "memory");
}

static __device__ __forceinline__ void ldsm4(uint32_t* r, uint32_t addr) {
    asm volatile("ldmatrix.sync.aligned.m8n8.x4.shared.b16 {%0,%1,%2,%3}, [%4];"
        : "=r"(r[0]), "=r"(r[1]), "=r"(r[2]), "=r"(r[3]) : "r"(addr));
}

static __device__ __forceinline__ void imma(int* d, const uint32_t* a,
                                            uint32_t b0, uint32_t b1) {
    asm volatile(
        "mma.sync.aligned.m16n8k32.row.col.s32.s8.s8.s32 "
        "{%0,%1,%2,%3}, {%4,%5,%6,%7}, {%8,%9}, {%0,%1,%2,%3};"
        : "+r"(d[0]), "+r"(d[1]), "+r"(d[2]), "+r"(d[3])
        : "r"(a[0]), "r"(a[1]), "r"(a[2]), "r"(a[3]), "r"(b0), "r"(b1));
}

static __device__ __forceinline__ void dp4x4(int* acc, const int4& a, const int4& b) {
    *acc = __dp4a(a.x, b.x, *acc);
    *acc = __dp4a(a.y, b.y, *acc);
    *acc = __dp4a(a.z, b.z, *acc);
    *acc = __dp4a(a.w, b.w, *acc);
}

// ---------------- geometry ----------------------------------------------------
static constexpr int      NCHUNK      = 32;       // 4096 / 128
static constexpr uint32_t CHUNK_BLK   = 16384;    // 128 rows x 128B per chunk-block
static constexpr uint32_t SLICE_BYTES = 8192;     // 64 rows x 128B
static constexpr int      STAGES      = 4;
static constexpr uint32_t OFF_A1      = 8192;
static constexpr uint32_t OFF_B       = 16384;
static constexpr uint32_t STAGE_BYTES = 24576;    // A0 8K + A1 8K + B 8K
static constexpr uint32_t OFF_FULL    = 0;
static constexpr uint32_t OFF_EMPTY   = 64;
static constexpr uint32_t OFF_STAGE   = 1024;
static constexpr uint32_t SMEM_DYN    = OFF_STAGE + STAGES * STAGE_BYTES;  // 99328

// ---------------- merged prologue: pack x (y=0) and sign(W) (y=1) ------------
__global__ void __launch_bounds__(256) prep_kernel(const float* __restrict__ x,
                                                   const float* __restrict__ w) {
    const int row = blockIdx.x;
    const int tid = threadIdx.x;
    const bool is_x = (blockIdx.y == 0);
    const float* src = (is_x ? x : w) + (size_t)row * 4096;

    float4 v[4];
    #pragma unroll
    for (int i = 0; i < 4; i++) v[i] = ((const float4*)src)[tid * 4 + i];

    const uint32_t inrow = (uint32_t)((tid & 7) * 16);
    const uint32_t swzc  = inrow ^ (uint32_t)((row & 7) << 4);
    const size_t off = ((size_t)(row >> 7) * 32 + (size_t)(tid >> 3)) * CHUNK_BLK
                     + (size_t)((row & 127) * 128) + swzc;

    if (is_x) {
        float mx = 0.f, sm = 0.f;
        #pragma unroll
        for (int i = 0; i < 4; i++) {
            mx = fmaxf(mx, fmaxf(fmaxf(fabsf(v[i].x), fabsf(v[i].y)),
                                 fmaxf(fabsf(v[i].z), fabsf(v[i].w))));
            sm += (v[i].x + v[i].y) + (v[i].z + v[i].w);
        }
        __shared__ float smax[256], ssum[256];
        smax[tid] = mx; ssum[tid] = sm;
        __syncthreads();
        for (int s = 128; s > 0; s >>= 1) {
            if (tid < s) {
                smax[tid] = fmaxf(smax[tid], smax[tid + s]);
                ssum[tid] += ssum[tid + s];
            }
            __syncthreads();
        }
        const float maxv = smax[0];
        const float inv  = (maxv > 0.f) ? 127.f / maxv : 0.f;

        uint32_t p1[4], p2[4];
        #pragma unroll
        for (int i = 0; i < 4; i++) {
            float e[4] = {v[i].x, v[i].y, v[i].z, v[i].w};
            uint32_t w1 = 0, w2 = 0;
            #pragma unroll
            for (int b = 0; b < 4; b++) {
                float r0 = e[b] * inv;
                int q1 = __float2int_rn(r0);
                int q2 = __float2int_rn((r0 - (float)q1) * 254.f);
                w1 |= (uint32_t)(q1 & 0xff) << (8 * b);
                w2 |= (uint32_t)(q2 & 0xff) << (8 * b);
            }
            p1[i] = w1; p2[i] = w2;
        }
        *(uint4*)((char*)g_a0 + off) = make_uint4(p1[0], p1[1], p1[2], p1[3]);
        *(uint4*)((char*)g_a1 + off) = make_uint4(p2[0], p2[1], p2[2], p2[3]);
        if (tid == 0) {
            g_scale[row]  = (maxv > 0.f) ? maxv / 127.f : 0.f;
            g_rowsum[row] = ssum[0];
        }
    } else {
        uint32_t p[4];
        #pragma unroll
        for (int i = 0; i < 4; i++) {
            float e[4] = {v[i].x, v[i].y, v[i].z, v[i].w};
            uint32_t wq = 0;
            #pragma unroll
            for (int b = 0; b < 4; b++) {
                int q = (e[b] > 0.f) ? 1 : ((e[b] < 0.f) ? -1 : 0);
                wq |= (uint32_t)(q & 0xff) << (8 * b);
            }
            p[i] = wq;
        }
        *(uint4*)((char*)g_b + off) = make_uint4(p[0], p[1], p[2], p[3]);
    }
}

// ---------------- main GEMM ----------------------------------------------------
// grid (64 ntile, 64 mtile), 256 threads, 2 CTAs/SM. CTA tile 64M x 64N.
// warps 0-3 (mma): warp w -> rows 16w..16w+15, cols 0..63 (8 imma/ks).
// warps 4-7 (dp):  warp d -> cols 16d..16d+15; lane -> rows {lane, lane+32}.
__global__ void __launch_bounds__(256, 2)
gemm_kernel(const float* __restrict__ wscale, const float* __restrict__ wbias,
            float* __restrict__ out) {
    extern __shared__ __align__(1024) char smem[];
    const uint32_t sb = smem_u32(smem);
    const int tid = threadIdx.x;
    const int wid = tid >> 5;
    const int lane = tid & 31;
    const int ntile = blockIdx.x;   // 0..63
    const int mtile = blockIdx.y;   // 0..63

    const char* pa0 = (const char*)g_a0 + (size_t)(mtile >> 1) * (32u * CHUNK_BLK)
                    + (size_t)(mtile & 1) * SLICE_BYTES;
    const char* pa1 = (const char*)g_a1 + (size_t)(mtile >> 1) * (32u * CHUNK_BLK)
                    + (size_t)(mtile & 1) * SLICE_BYTES;
    const char* pb  = (const char*)g_b  + (size_t)(ntile >> 1) * (32u * CHUNK_BLK)
                    + (size_t)(ntile & 1) * SLICE_BYTES;

    if (tid == 0) {
        #pragma unroll
        for (int s = 0; s < STAGES; s++) {
            MBARRIER_INIT(sb + OFF_FULL  + 8u * s, 1);
            MBARRIER_INIT(sb + OFF_EMPTY + 8u * s, 8);
        }
    }
    __syncthreads();

    if (tid == 0) {
        #pragma unroll
        for (int s = 0; s < STAGES; s++) {
            uint32_t fb = sb + OFF_FULL + 8u * s;
            MBARRIER_EXPECT_TX(fb, STAGE_BYTES);
            uint32_t dst = sb + OFF_STAGE + (uint32_t)s * STAGE_BYTES;
            size_t co = (size_t)s * CHUNK_BLK;
            bulk_g2s(dst,          pa0 + co, SLICE_BYTES, fb);
            bulk_g2s(dst + OFF_A1, pa1 + co, SLICE_BYTES, fb);
            bulk_g2s(dst + OFF_B,  pb  + co, SLICE_BYTES, fb);
        }
    }

    if (wid < 4) {
        // ============ MMA warps: level-1, rows 16w..16w+15, cols 0..63 =========
        const int rA = lane & 15;
        const uint32_t hb = (uint32_t)((lane >> 4) * 16);
        const uint32_t ph_sw = (uint32_t)((rA & 7) << 4);

        const uint32_t rowA = (uint32_t)((wid * 16 + rA) * 128);
        uint32_t rowB[4];
        #pragma unroll
        for (int j = 0; j < 4; j++) rowB[j] = (uint32_t)((j * 16 + rA) * 128);
        uint32_t colx[4];
        #pragma unroll
        for (int ks = 0; ks < 4; ks++) colx[ks] = ((uint32_t)(ks * 32) + hb) ^ ph_sw;

        int acc0[8][4];                   // 32 regs: 8 n8-tiles of cols 0..63
        #pragma unroll
        for (int u = 0; u < 8; u++)
            #pragma unroll
            for (int i = 0; i < 4; i++) acc0[u][i] = 0;

        for (int ch = 0; ch < NCHUNK; ch++) {
            const int st = ch & 3;
            const int ph = (ch >> 2) & 1;
            MBARRIER_WAIT_PARITY(sb + OFF_FULL + 8u * st, ph);
            const uint32_t SA0 = sb + OFF_STAGE + (uint32_t)st * STAGE_BYTES;
            const uint32_t SB  = SA0 + OFF_B;

            #pragma unroll
            for (int ks = 0; ks < 4; ks++) {
                uint32_t a0f[4], bf[4][4];
                ldsm4(a0f, SA0 + rowA + colx[ks]);
                #pragma unroll
                for (int j = 0; j < 4; j++) ldsm4(bf[j], SB + rowB[j] + colx[ks]);
                #pragma unroll
                for (int j = 0; j < 4; j++) {
                    imma(acc0[2 * j],     a0f, bf[j][0], bf[j][2]);
                    imma(acc0[2 * j + 1], a0f, bf[j][1], bf[j][3]);
                }
            }
            if (lane == 0) MBARRIER_ARRIVE(sb + OFF_EMPTY + 8u * st);
            if (tid == 0 && ch + STAGES < NCHUNK) {
                MBARRIER_WAIT_PARITY_RELAXED(sb + OFF_EMPTY + 8u * st, ph);
                uint32_t fb = sb + OFF_FULL + 8u * st;
                MBARRIER_EXPECT_TX(fb, STAGE_BYTES);
                uint32_t dst = sb + OFF_STAGE + (uint32_t)st * STAGE_BYTES;
                size_t co = (size_t)(ch + STAGES) * CHUNK_BLK;
                bulk_g2s(dst,          pa0 + co, SLICE_BYTES, fb);
                bulk_g2s(dst + OFF_A1, pa1 + co, SLICE_BYTES, fb);
                bulk_g2s(dst + OFF_B,  pb  + co, SLICE_BYTES, fb);
            }
        }

        // ---- epilogue (mma warps combine + store) ----
        __syncthreads();                   // dp warps done; sInt being written
        __syncthreads();                   // sInt complete
        const int* sInt = (const int*)smem;   // 64 x 68 ints
        const float inv254 = 1.f / 254.f;
        const int lg = lane >> 2;
        const int lc = (lane & 3) * 2;
        #pragma unroll
        for (int half = 0; half < 2; half++) {
            const int ml = wid * 16 + lg + half * 8;
            const int m  = mtile * 64 + ml;
            const float alpha = g_scale[m];
            const float rs    = g_rowsum[m];
            float* orow = out + (size_t)m * 4096;
            const int i0 = half * 2, i1 = half * 2 + 1;
            #pragma unroll
            for (int u = 0; u < 8; u++) {
                const int nl = u * 8 + lc;
                const int n  = ntile * 64 + nl;
                float v0 = (float)acc0[u][i0] + (float)sInt[ml * 68 + nl]     * inv254;
                float v1 = (float)acc0[u][i1] + (float)sInt[ml * 68 + nl + 1] * inv254;
                float2 o;
                o.x = __ldg(wscale + n)     * (alpha * v0) + __ldg(wbias + n)     * rs;
                o.y = __ldg(wscale + n + 1) * (alpha * v1) + __ldg(wbias + n + 1) * rs;
                *(float2*)(orow + n) = o;
            }
        }
    } else {
        // ===== DP warps: level-2, warp d -> cols 16d..16d+15 ====================
        const int dwid = wid - 4;                     // 0..3
        const uint32_t aswz = (uint32_t)((lane & 7) * 16);

        int accL[2][16];                   // 32 regs
        #pragma unroll
        for (int i = 0; i < 2; i++)
            #pragma unroll
            for (int j = 0; j < 16; j++) accL[i][j] = 0;

        for (int ch = 0; ch < NCHUNK; ch++) {
            const int st = ch & 3;
            const int ph = (ch >> 2) & 1;
            MBARRIER_WAIT_PARITY(sb + OFF_FULL + 8u * st, ph);
            const char* cSA1 = smem + OFF_STAGE + (uint32_t)st * STAGE_BYTES + OFF_A1;
            const char* cSB  = smem + OFF_STAGE + (uint32_t)st * STAGE_BYTES + OFF_B;

            #pragma unroll
            for (int ks = 0; ks < 4; ks++) {
                #pragma unroll
                for (int sub = 0; sub < 2; sub++) {
                    const uint32_t col = (uint32_t)(ks * 32 + sub * 16);
                    int4 a4[2];
                    a4[0] = *(const int4*)(cSA1 + lane * 128 + (col ^ aswz));
                    a4[1] = *(const int4*)(cSA1 + (lane + 32) * 128 + (col ^ aswz));
                    #pragma unroll
                    for (int j = 0; j < 16; j++) {
                        // b row = dwid*16 + j; (row & 7) == (j & 7).
                        const int4 b4 = *(const int4*)(cSB + (dwid * 16 + j) * 128
                                                       + (col ^ (uint32_t)((j & 7) * 16)));
                        dp4x4(&accL[0][j], a4[0], b4);
                        dp4x4(&accL[1][j], a4[1], b4);
                    }
                }
            }
            if (lane == 0) MBARRIER_ARRIVE(sb + OFF_EMPTY + 8u * st);
        }

        // ---- publish level-2 sums for the mma warps ----
        __syncthreads();                   // everyone done with stage buffers
        int* sInt = (int*)smem;            // 64 x 68 ints
        #pragma unroll
        for (int i = 0; i < 2; i++) {
            const int row = lane + 32 * i;
            #pragma unroll
            for (int j = 0; j < 16; j++)
                sInt[row * 68 + (dwid * 16 + j)] = accL[i][j];
        }
        __syncthreads();
    }
}

// ---------------- launch --------------------------------------------------------
extern "C" void kernel_launch(void* const* d_in, const int* in_sizes, int n_in,
                              void* d_out, int out_size) {
    (void)in_sizes; (void)n_in; (void)out_size;
    const float* x      = (const float*)d_in[0];   // [2,2048,4096]
    const float* weight = (const float*)d_in[1];   // [4096,4096]
    const float* wscale = (const float*)d_in[2];   // [4096,1]
    const float* wbias  = (const float*)d_in[3];   // [4096,1]
    float* out = (float*)d_out;

    cudaFuncSetAttribute(gemm_kernel, cudaFuncAttributeMaxDynamicSharedMemorySize,
                         (int)SMEM_DYN);

    prep_kernel<<<dim3(4096, 2), 256>>>(x, weight);
    gemm_kernel<<<dim3(64, 64), 256, SMEM_DYN>>>(wscale, wbias, out);
}